// round 1
// baseline (speedup 1.0000x reference)
#include <cuda_runtime.h>

#define BATCH 4
#define NPTS 4096
#define KOUT 16
#define NEED 31            // rank 0 plus ranks 16..30
#define R2 256.0f
#define BPB 128            // knn blocks per batch

// scratch: dilated ids [B, N, K]
__device__ int g_ids[BATCH * NPTS * KOUT];

// ---------------------------------------------------------------------------
// Kernel 1: ball query + dilated id selection. One warp per query point.
// smem: float4 per point = (x, y, z, |p|^2), 64KB per block (one batch).
// ---------------------------------------------------------------------------
__global__ void knn_kernel(const float* __restrict__ xyz) {
    extern __shared__ float4 s[];            // NPTS float4 = 64KB
    __shared__ int regbuf[8][15];            // per-warp ranks 16..30

    int b   = blockIdx.x / BPB;
    int blk = blockIdx.x % BPB;
    const float* xb = xyz + (size_t)b * NPTS * 3;

    // cooperative load + squared-norm precompute (exact fp32, no FMA)
    for (int i = threadIdx.x; i < NPTS; i += blockDim.x) {
        float x = xb[3 * i + 0];
        float y = xb[3 * i + 1];
        float z = xb[3 * i + 2];
        float q = __fadd_rn(__fadd_rn(__fmul_rn(x, x), __fmul_rn(y, y)),
                            __fmul_rn(z, z));
        s[i] = make_float4(x, y, z, q);
    }
    __syncthreads();

    int warp = threadIdx.x >> 5;
    int lane = threadIdx.x & 31;
    int wpb  = blockDim.x >> 5;              // warps per block (8)
    unsigned lt = (1u << lane) - 1u;

    for (int n = blk * wpb + warp; n < NPTS; n += BPB * wpb) {
        float4 pn = s[n];
        int cnt = 0;
        int first = 0;

        for (int base = 0; base < NPTS; base += 32) {
            float4 pm = s[base + lane];
            float dot = __fadd_rn(
                __fadd_rn(__fmul_rn(pn.x, pm.x), __fmul_rn(pn.y, pm.y)),
                __fmul_rn(pn.z, pm.z));
            float d2 = __fsub_rn(__fadd_rn(pn.w, pm.w), __fmul_rn(2.0f, dot));
            unsigned mask = __ballot_sync(0xffffffffu, d2 < R2);
            if (mask) {
                if (cnt == 0) first = base + __ffs(mask) - 1;
                if ((mask >> lane) & 1u) {
                    int r = cnt + __popc(mask & lt);
                    if (r >= 16 && r < 31) regbuf[warp][r - 16] = base + lane;
                }
                cnt += __popc(mask);
                if (cnt >= NEED) break;
            }
        }
        __syncwarp();
        if (lane < KOUT) {
            int v = first;                               // rank 0 / padding
            if (lane > 0 && cnt >= lane + 16)            // rank lane+15 exists
                v = regbuf[warp][lane - 1];
            g_ids[((b * NPTS) + n) * KOUT + lane] = v;
        }
        __syncwarp();
    }
}

// ---------------------------------------------------------------------------
// Kernel 2: gather. One thread per (b, n, k). Writes are coalesced per
// channel because consecutive threads hold consecutive (n,k).
// Output layout: [B,3,N,K] xyz block followed by [B,64,N,K] feature block.
// ---------------------------------------------------------------------------
__global__ void gather_kernel(const float* __restrict__ xyz,
                              const float* __restrict__ feat,
                              float* __restrict__ out) {
    int t = blockIdx.x * blockDim.x + threadIdx.x;
    if (t >= BATCH * NPTS * KOUT) return;

    int k = t & (KOUT - 1);
    int n = (t >> 4) & (NPTS - 1);
    int b = t >> 16;                         // NPTS*KOUT = 65536 = 2^16
    int idx = g_ids[t];

    const size_t NK = (size_t)NPTS * KOUT;   // 65536

    // xyz part: out[((b*3 + c)*N + n)*K + k]
    const float* xr = xyz + ((size_t)b * NPTS + idx) * 3;
#pragma unroll
    for (int c = 0; c < 3; c++)
        out[(((size_t)b * 3 + c) * NPTS + n) * KOUT + k] = xr[c];

    // feature part
    float* of = out + (size_t)BATCH * 3 * NK;
    const float4* fr =
        (const float4*)(feat + ((size_t)b * NPTS + idx) * 64);
    size_t o0 = ((size_t)b * 64) * NK + (size_t)n * KOUT + k;
#pragma unroll
    for (int c4 = 0; c4 < 16; c4++) {
        float4 v = fr[c4];
        size_t oc = o0 + (size_t)(c4 * 4) * NK;
        of[oc]          = v.x;
        of[oc + NK]     = v.y;
        of[oc + 2 * NK] = v.z;
        of[oc + 3 * NK] = v.w;
    }
}

extern "C" void kernel_launch(void* const* d_in, const int* in_sizes, int n_in,
                              void* d_out, int out_size) {
    const float* xyz  = (const float*)d_in[0];
    const float* feat = (const float*)d_in[1];
    float* out = (float*)d_out;

    cudaFuncSetAttribute(knn_kernel,
                         cudaFuncAttributeMaxDynamicSharedMemorySize,
                         NPTS * sizeof(float4));

    knn_kernel<<<BATCH * BPB, 256, NPTS * sizeof(float4)>>>(xyz);

    int total = BATCH * NPTS * KOUT;
    gather_kernel<<<(total + 255) / 256, 256>>>(xyz, feat, out);
}

// round 2
// speedup vs baseline: 1.4766x; 1.4766x over previous
#include <cuda_runtime.h>

#define BATCH 4
#define NPTS 4096
#define KOUT 16
#define NEED 31            // rank 0 plus ranks 16..30
#define R2 256.0f
#define NTILES (NPTS / 32) // 128
#define WARPS 8
#define NBLOCKS 444        // 148 SMs * 3 resident blocks

// scratch: dilated ids [B, N, K] and per-batch steal counters
__device__ int g_ids[BATCH * NPTS * KOUT];
__device__ int g_ctr[BATCH];

__global__ void init_kernel() {
    if (threadIdx.x < BATCH) g_ctr[threadIdx.x] = 0;
}

// exact arithmetic (matches reference decisions; rel_err was 0.0 with this)
__device__ __forceinline__ float dist2(float4 a, float4 b) {
    float dot = __fadd_rn(
        __fadd_rn(__fmul_rn(a.x, b.x), __fmul_rn(a.y, b.y)),
        __fmul_rn(a.z, b.z));
    return __fsub_rn(__fadd_rn(a.w, b.w), __fmul_rn(2.0f, dot));
}

// ---------------------------------------------------------------------------
// Kernel 1: ball query + dilated id selection.
// Warp per query, work-stealing within a batch. 4-tile unrolled scan writes
// ballot words to smem; a short decode phase extracts rank 0 and 16..30.
// ---------------------------------------------------------------------------
__global__ void __launch_bounds__(256) knn_kernel(const float* __restrict__ xyz) {
    extern __shared__ float4 s[];                       // 4096 float4 = 64KB
    __shared__ __align__(16) unsigned words[WARPS][NTILES];
    __shared__ int oid[WARPS][KOUT];

    int b = blockIdx.x % BATCH;
    const float* xb = xyz + (size_t)b * NPTS * 3;

    for (int i = threadIdx.x; i < NPTS; i += blockDim.x) {
        float x = xb[3 * i + 0];
        float y = xb[3 * i + 1];
        float z = xb[3 * i + 2];
        float q = __fadd_rn(__fadd_rn(__fmul_rn(x, x), __fmul_rn(y, y)),
                            __fmul_rn(z, z));
        s[i] = make_float4(x, y, z, q);
    }
    __syncthreads();

    int warp = threadIdx.x >> 5;
    int lane = threadIdx.x & 31;

    for (;;) {
        int q = 0;
        if (lane == 0) q = atomicAdd(&g_ctr[b], 1);
        q = __shfl_sync(0xffffffffu, q, 0);
        if (q >= NPTS) break;

        // zero mask words (covers unscanned tiles for the decode phase)
#pragma unroll
        for (int i = 0; i < 4; i++) words[warp][lane + 32 * i] = 0u;
        __syncwarp();

        float4 pn = s[q];
        int cnt = 0;

        // ---- scan: 4 tiles (128 candidates) per iteration ----
        for (int c = 0; c < NTILES; c += 4) {
            float4 p0 = s[(c + 0) * 32 + lane];
            float4 p1 = s[(c + 1) * 32 + lane];
            float4 p2 = s[(c + 2) * 32 + lane];
            float4 p3 = s[(c + 3) * 32 + lane];
            float d0 = dist2(pn, p0);
            float d1 = dist2(pn, p1);
            float d2 = dist2(pn, p2);
            float d3 = dist2(pn, p3);
            unsigned m0 = __ballot_sync(0xffffffffu, d0 < R2);
            unsigned m1 = __ballot_sync(0xffffffffu, d1 < R2);
            unsigned m2 = __ballot_sync(0xffffffffu, d2 < R2);
            unsigned m3 = __ballot_sync(0xffffffffu, d3 < R2);
            if (lane == 0)
                *(uint4*)&words[warp][c] = make_uint4(m0, m1, m2, m3);
            cnt += __popc(m0) + __popc(m1) + __popc(m2) + __popc(m3);
            if (cnt >= NEED) break;
        }
        __syncwarp();

        // ---- decode: find rank 0 and ranks 16..30 from mask words ----
        int base = 0;
#pragma unroll
        for (int g = 0; g < 4; g++) {
            if (base >= NEED) break;
            unsigned w = words[warp][32 * g + lane];
            int pc = __popc(w);
            int pre = pc;                          // inclusive warp scan
#pragma unroll
            for (int o = 1; o < 32; o <<= 1) {
                int t = __shfl_up_sync(0xffffffffu, pre, o);
                if (lane >= o) pre += t;
            }
            int lo = base + pre - pc;              // first rank in my word
            if (w && lo < NEED) {
                unsigned ww = w;
                int r = lo;
                while (ww && r < NEED) {
                    int bit = __ffs(ww) - 1;
                    ww &= ww - 1;
                    if (r == 0)
                        oid[warp][0] = 32 * (32 * g + lane) + bit;
                    else if (r >= 16)
                        oid[warp][r - 15] = 32 * (32 * g + lane) + bit;
                    r++;
                }
            }
            base += __shfl_sync(0xffffffffu, pre, 31);
        }
        __syncwarp();

        if (lane < KOUT) {
            int v = (lane > 0 && cnt >= lane + 16) ? oid[warp][lane]
                                                   : oid[warp][0];
            g_ids[((b * NPTS) + q) * KOUT + lane] = v;
        }
        __syncwarp();
    }
}

// ---------------------------------------------------------------------------
// Kernel 2: gather. Thread per (b,n,k); two rounds of 8 in-flight LDG.128.
// Writes coalesced 128B per warp per channel.
// ---------------------------------------------------------------------------
__global__ void __launch_bounds__(256) gather_kernel(
        const float* __restrict__ xyz,
        const float* __restrict__ feat,
        float* __restrict__ out) {
    int t = blockIdx.x * blockDim.x + threadIdx.x;

    int k = t & (KOUT - 1);
    int n = (t >> 4) & (NPTS - 1);
    int b = t >> 16;
    int idx = g_ids[t];

    const size_t NK = (size_t)NPTS * KOUT;   // 65536

    // xyz part: out[((b*3 + c)*N + n)*K + k]
    const float* xr = xyz + ((size_t)b * NPTS + idx) * 3;
    float x0 = xr[0], x1 = xr[1], x2 = xr[2];
    size_t ox = (((size_t)b * 3) * NPTS + n) * KOUT + k;
    out[ox]              = x0;
    out[ox + NK]         = x1;
    out[ox + 2 * NK]     = x2;

    // feature part
    float* of = out + (size_t)BATCH * 3 * NK;
    const float4* fr = (const float4*)(feat + ((size_t)b * NPTS + idx) * 64);
    size_t o0 = ((size_t)b * 64) * NK + (size_t)n * KOUT + k;

    float4 v[8];
#pragma unroll
    for (int i = 0; i < 8; i++) v[i] = fr[i];
#pragma unroll
    for (int i = 0; i < 8; i++) {
        size_t oc = o0 + (size_t)(i * 4) * NK;
        of[oc]          = v[i].x;
        of[oc + NK]     = v[i].y;
        of[oc + 2 * NK] = v[i].z;
        of[oc + 3 * NK] = v[i].w;
    }
#pragma unroll
    for (int i = 0; i < 8; i++) v[i] = fr[8 + i];
#pragma unroll
    for (int i = 0; i < 8; i++) {
        size_t oc = o0 + (size_t)((8 + i) * 4) * NK;
        of[oc]          = v[i].x;
        of[oc + NK]     = v[i].y;
        of[oc + 2 * NK] = v[i].z;
        of[oc + 3 * NK] = v[i].w;
    }
}

extern "C" void kernel_launch(void* const* d_in, const int* in_sizes, int n_in,
                              void* d_out, int out_size) {
    const float* xyz  = (const float*)d_in[0];
    const float* feat = (const float*)d_in[1];
    float* out = (float*)d_out;

    cudaFuncSetAttribute(knn_kernel,
                         cudaFuncAttributeMaxDynamicSharedMemorySize,
                         NPTS * sizeof(float4));

    init_kernel<<<1, 32>>>();
    knn_kernel<<<NBLOCKS, 256, NPTS * sizeof(float4)>>>(xyz);

    int total = BATCH * NPTS * KOUT;
    gather_kernel<<<(total + 255) / 256, 256>>>(xyz, feat, out);
}

// round 3
// speedup vs baseline: 1.7165x; 1.1624x over previous
#include <cuda_runtime.h>

#define BATCH 4
#define NPTS 4096
#define KOUT 16
#define NEED 31                 // rank 0 plus ranks 16..30
#define R2 256.0f
#define NTILES (NPTS / 32)      // 128
#define WARPS 8
#define NBLOCKS 444             // 148 SMs * 3 resident blocks
#define WPB_PER_BATCH ((NBLOCKS / BATCH) * WARPS)        // 888
#define PERIOD (NPTS + WPB_PER_BATCH)                    // 4984
#define NK ((size_t)NPTS * KOUT)                         // 65536

// steal counters: never reset; q = ctr % PERIOD is deterministic per replay
__device__ unsigned g_ctr[BATCH];

// exact arithmetic (matches reference decisions; rel_err 0.0 with this)
__device__ __forceinline__ float dist2(float4 a, float4 b) {
    float dot = __fadd_rn(
        __fadd_rn(__fmul_rn(a.x, b.x), __fmul_rn(a.y, b.y)),
        __fmul_rn(a.z, b.z));
    return __fsub_rn(__fadd_rn(a.w, b.w), __fmul_rn(2.0f, dot));
}

// ---------------------------------------------------------------------------
// Fused kernel: ball query + dilated selection + gather epilogue.
// Warp per query (work-stealing). Scan -> ballot words -> decode -> gather.
// ---------------------------------------------------------------------------
__global__ void __launch_bounds__(256) fused_kernel(
        const float* __restrict__ xyz,
        const float* __restrict__ feat,
        float* __restrict__ out) {
    extern __shared__ float4 s[];                       // 4096 float4 = 64KB
    __shared__ __align__(16) unsigned words[WARPS][NTILES];
    __shared__ int oid[WARPS][KOUT + 1];

    int b = blockIdx.x % BATCH;
    const float* xb = xyz + (size_t)b * NPTS * 3;

    for (int i = threadIdx.x; i < NPTS; i += blockDim.x) {
        float x = xb[3 * i + 0];
        float y = xb[3 * i + 1];
        float z = xb[3 * i + 2];
        float nq = __fadd_rn(__fadd_rn(__fmul_rn(x, x), __fmul_rn(y, y)),
                             __fmul_rn(z, z));
        s[i] = make_float4(x, y, z, nq);
    }
    __syncthreads();

    int warp = threadIdx.x >> 5;
    int lane = threadIdx.x & 31;
    const float* fb = feat + (size_t)b * NPTS * 64;
    float* outx = out + ((size_t)b * 3) * NK;                 // xyz block
    float* outf = out + (size_t)BATCH * 3 * NK + ((size_t)b * 64) * NK;

    for (;;) {
        unsigned qr = 0;
        if (lane == 0) qr = atomicAdd(&g_ctr[b], 1u) % PERIOD;
        int q = __shfl_sync(0xffffffffu, (int)qr, 0);
        if (q >= NPTS) break;

        float4 pn = s[q];
        int cnt = 0;
        int tscan = NTILES;

        // ---- scan: 4 tiles (128 candidates) per iteration ----
        for (int c = 0; c < NTILES; c += 4) {
            float4 p0 = s[(c + 0) * 32 + lane];
            float4 p1 = s[(c + 1) * 32 + lane];
            float4 p2 = s[(c + 2) * 32 + lane];
            float4 p3 = s[(c + 3) * 32 + lane];
            float d0 = dist2(pn, p0);
            float d1 = dist2(pn, p1);
            float d2 = dist2(pn, p2);
            float d3 = dist2(pn, p3);
            unsigned m0 = __ballot_sync(0xffffffffu, d0 < R2);
            unsigned m1 = __ballot_sync(0xffffffffu, d1 < R2);
            unsigned m2 = __ballot_sync(0xffffffffu, d2 < R2);
            unsigned m3 = __ballot_sync(0xffffffffu, d3 < R2);
            if (lane == 0)
                *(uint4*)&words[warp][c] = make_uint4(m0, m1, m2, m3);
            cnt += __popc(m0) + __popc(m1) + __popc(m2) + __popc(m3);
            if (cnt >= NEED) { tscan = c + 4; break; }
        }
        __syncwarp();

        // ---- decode: rank 0 and ranks 16..30 from mask words ----
        int base = 0;
#pragma unroll
        for (int g = 0; g < 4; g++) {
            if (base >= NEED) break;
            int wi = 32 * g + lane;
            unsigned w = (wi < tscan) ? words[warp][wi] : 0u;
            int pc = __popc(w);
            int pre = pc;                          // inclusive warp scan
#pragma unroll
            for (int o = 1; o < 32; o <<= 1) {
                int t = __shfl_up_sync(0xffffffffu, pre, o);
                if (lane >= o) pre += t;
            }
            int lo = base + pre - pc;              // first rank in my word
            if (w && lo < NEED) {
                unsigned ww = w;
                int r = lo;
                while (ww && r < NEED) {
                    int bit = __ffs(ww) - 1;
                    ww &= ww - 1;
                    if (r == 0)
                        oid[warp][0] = 32 * wi + bit;
                    else if (r >= 16)
                        oid[warp][r - 15] = 32 * wi + bit;
                    r++;
                }
            }
            base += __shfl_sync(0xffffffffu, pre, 31);
        }
        __syncwarp();

        // finalize ids (padding with first hit) back into oid[warp][k]
        if (lane < KOUT) {
            int v = (lane > 0 && cnt >= lane + 16) ? oid[warp][lane]
                                                   : oid[warp][0];
            oid[warp][lane] = v;
        }
        __syncwarp();

        // ---- gather epilogue ----
        // xyz: straight from smem (lanes 0..15, k = lane)
        if (lane < KOUT) {
            float4 p = s[oid[warp][lane]];
            size_t ox = (size_t)q * KOUT + lane;
            outx[ox]          = p.x;
            outx[ox + NK]     = p.y;
            outx[ox + 2 * NK] = p.z;
        }

        // feat: lane l owns (k = l>>1, half = l&1) -> 32 channels
        {
            int k    = lane >> 1;
            int half = lane & 1;
            int id   = oid[warp][k];
            const float4* fr = (const float4*)(fb + (size_t)id * 64) + half * 8;
            float* ob = outf + (size_t)(half * 32) * NK + (size_t)q * KOUT + k;
#pragma unroll
            for (int ch = 0; ch < 2; ch++) {
                float4 v0 = fr[ch * 4 + 0];
                float4 v1 = fr[ch * 4 + 1];
                float4 v2 = fr[ch * 4 + 2];
                float4 v3 = fr[ch * 4 + 3];
                float* o = ob + (size_t)(ch * 16) * NK;
                o[0 * NK]  = v0.x; o[1 * NK]  = v0.y;
                o[2 * NK]  = v0.z; o[3 * NK]  = v0.w;
                o[4 * NK]  = v1.x; o[5 * NK]  = v1.y;
                o[6 * NK]  = v1.z; o[7 * NK]  = v1.w;
                o[8 * NK]  = v2.x; o[9 * NK]  = v2.y;
                o[10 * NK] = v2.z; o[11 * NK] = v2.w;
                o[12 * NK] = v3.x; o[13 * NK] = v3.y;
                o[14 * NK] = v3.z; o[15 * NK] = v3.w;
            }
        }
        __syncwarp();
    }
}

extern "C" void kernel_launch(void* const* d_in, const int* in_sizes, int n_in,
                              void* d_out, int out_size) {
    const float* xyz  = (const float*)d_in[0];
    const float* feat = (const float*)d_in[1];
    float* out = (float*)d_out;

    cudaFuncSetAttribute(fused_kernel,
                         cudaFuncAttributeMaxDynamicSharedMemorySize,
                         NPTS * sizeof(float4));

    fused_kernel<<<NBLOCKS, 256, NPTS * sizeof(float4)>>>(xyz, feat, out);
}

// round 4
// speedup vs baseline: 1.8151x; 1.0575x over previous
#include <cuda_runtime.h>

#define BATCH 4
#define NPTS 4096
#define KOUT 16
#define NEED 31                 // rank 0 plus ranks 16..30
#define R2 256.0f
#define NTILES (NPTS / 32)      // 128
#define TPB 512
#define WARPS (TPB / 32)        // 16
#define NBLOCKS 444             // 148 SMs * 3 resident blocks
#define WPB_PER_BATCH ((NBLOCKS / BATCH) * WARPS)        // 1776
#define PERIOD (NPTS + WPB_PER_BATCH)                    // 5872
#define NK ((size_t)NPTS * KOUT)                         // 65536

// steal counters: never reset; q = ctr % PERIOD is deterministic per replay
__device__ unsigned g_ctr[BATCH];

// exact arithmetic (matches reference decisions; rel_err 0.0 with this)
__device__ __forceinline__ float dist2(float4 a, float4 b) {
    float dot = __fadd_rn(
        __fadd_rn(__fmul_rn(a.x, b.x), __fmul_rn(a.y, b.y)),
        __fmul_rn(a.z, b.z));
    return __fsub_rn(__fadd_rn(a.w, b.w), __fmul_rn(2.0f, dot));
}

// ---------------------------------------------------------------------------
// Fused kernel: ball query + dilated selection + gather epilogue.
// Warp per query (work-stealing). Scan -> ballot words -> decode -> gather.
// ---------------------------------------------------------------------------
__global__ void __launch_bounds__(TPB, 3) fused_kernel(
        const float* __restrict__ xyz,
        const float* __restrict__ feat,
        float* __restrict__ out) {
    extern __shared__ float4 s[];                       // 4096 float4 = 64KB
    __shared__ __align__(16) unsigned words[WARPS][NTILES];
    __shared__ int oid[WARPS][KOUT + 1];

    int b = blockIdx.x % BATCH;
    const float* xb = xyz + (size_t)b * NPTS * 3;

    for (int i = threadIdx.x; i < NPTS; i += blockDim.x) {
        float x = xb[3 * i + 0];
        float y = xb[3 * i + 1];
        float z = xb[3 * i + 2];
        float nq = __fadd_rn(__fadd_rn(__fmul_rn(x, x), __fmul_rn(y, y)),
                             __fmul_rn(z, z));
        s[i] = make_float4(x, y, z, nq);
    }
    __syncthreads();

    int warp = threadIdx.x >> 5;
    int lane = threadIdx.x & 31;
    const float* fb = feat + (size_t)b * NPTS * 64;
    float* outx = out + ((size_t)b * 3) * NK;                 // xyz block
    float* outf = out + (size_t)BATCH * 3 * NK + ((size_t)b * 64) * NK;

    for (;;) {
        unsigned qr = 0;
        if (lane == 0) qr = atomicAdd(&g_ctr[b], 1u) % PERIOD;
        int q = __shfl_sync(0xffffffffu, (int)qr, 0);
        if (q >= NPTS) break;

        float4 pn = s[q];
        int cnt = 0;
        int tscan = NTILES;

        // ---- scan: 4 tiles (128 candidates) per iteration ----
        {
            const float4* sp = s + lane;
            for (int c = 0; c < NTILES; c += 4, sp += 128) {
                float4 p0 = sp[0];
                float4 p1 = sp[32];
                float4 p2 = sp[64];
                float4 p3 = sp[96];
                float d0 = dist2(pn, p0);
                float d1 = dist2(pn, p1);
                float d2 = dist2(pn, p2);
                float d3 = dist2(pn, p3);
                unsigned m0 = __ballot_sync(0xffffffffu, d0 < R2);
                unsigned m1 = __ballot_sync(0xffffffffu, d1 < R2);
                unsigned m2 = __ballot_sync(0xffffffffu, d2 < R2);
                unsigned m3 = __ballot_sync(0xffffffffu, d3 < R2);
                if (lane == 0)
                    *(uint4*)&words[warp][c] = make_uint4(m0, m1, m2, m3);
                cnt += __popc(m0) + __popc(m1) + __popc(m2) + __popc(m3);
                if (cnt >= NEED) { tscan = c + 4; break; }
            }
        }
        __syncwarp();

        // ---- decode: rank 0 and ranks 16..30 from mask words ----
        int base = 0;
#pragma unroll
        for (int g = 0; g < 4; g++) {
            if (base >= NEED) break;
            int wi = 32 * g + lane;
            unsigned w = (wi < tscan) ? words[warp][wi] : 0u;
            int pc = __popc(w);
            int pre = pc;                          // inclusive warp scan
#pragma unroll
            for (int o = 1; o < 32; o <<= 1) {
                int t = __shfl_up_sync(0xffffffffu, pre, o);
                if (lane >= o) pre += t;
            }
            int lo = base + pre - pc;              // first rank in my word
            if (w && lo < NEED) {
                unsigned ww = w;
                int r = lo;
                while (ww && r < NEED) {
                    int bit = __ffs(ww) - 1;
                    ww &= ww - 1;
                    if (r == 0)
                        oid[warp][0] = 32 * wi + bit;
                    else if (r >= 16)
                        oid[warp][r - 15] = 32 * wi + bit;
                    r++;
                }
            }
            base += __shfl_sync(0xffffffffu, pre, 31);
        }
        __syncwarp();

        // finalize ids (padding with first hit) back into oid[warp][k]
        if (lane < KOUT) {
            int v = (lane > 0 && cnt >= lane + 16) ? oid[warp][lane]
                                                   : oid[warp][0];
            oid[warp][lane] = v;
        }
        __syncwarp();

        // ---- gather epilogue ----
        // xyz: straight from smem (lanes 0..15, k = lane)
        if (lane < KOUT) {
            float4 p = s[oid[warp][lane]];
            size_t ox = (size_t)q * KOUT + lane;
            outx[ox]          = p.x;
            outx[ox + NK]     = p.y;
            outx[ox + 2 * NK] = p.z;
        }

        // feat: lane l owns (k = l>>1, half = l&1) -> 32 channels
        {
            int k    = lane >> 1;
            int half = lane & 1;
            int id   = oid[warp][k];
            const float4* fr = (const float4*)(fb + (size_t)id * 64) + half * 8;
            float* ob = outf + (size_t)(half * 32) * NK + (size_t)q * KOUT + k;
#pragma unroll
            for (int ch = 0; ch < 2; ch++) {
                float4 v0 = fr[ch * 4 + 0];
                float4 v1 = fr[ch * 4 + 1];
                float4 v2 = fr[ch * 4 + 2];
                float4 v3 = fr[ch * 4 + 3];
                float* o = ob + (size_t)(ch * 16) * NK;
                o[0 * NK]  = v0.x; o[1 * NK]  = v0.y;
                o[2 * NK]  = v0.z; o[3 * NK]  = v0.w;
                o[4 * NK]  = v1.x; o[5 * NK]  = v1.y;
                o[6 * NK]  = v1.z; o[7 * NK]  = v1.w;
                o[8 * NK]  = v2.x; o[9 * NK]  = v2.y;
                o[10 * NK] = v2.z; o[11 * NK] = v2.w;
                o[12 * NK] = v3.x; o[13 * NK] = v3.y;
                o[14 * NK] = v3.z; o[15 * NK] = v3.w;
            }
        }
        __syncwarp();
    }
}

extern "C" void kernel_launch(void* const* d_in, const int* in_sizes, int n_in,
                              void* d_out, int out_size) {
    const float* xyz  = (const float*)d_in[0];
    const float* feat = (const float*)d_in[1];
    float* out = (float*)d_out;

    cudaFuncSetAttribute(fused_kernel,
                         cudaFuncAttributeMaxDynamicSharedMemorySize,
                         NPTS * sizeof(float4));

    fused_kernel<<<NBLOCKS, TPB, NPTS * sizeof(float4)>>>(xyz, feat, out);
}